// round 2
// baseline (speedup 1.0000x reference)
#include <cuda_runtime.h>
#include <cstdint>

#define NNODES 50000
#define NEDGES 800000
#define SS 2
#define DH0 192   /* 128 + 64 */
#define DH1 256
#define MROWS (SS*NNODES)          /* 100000 */
#define OUT_MAIN ((size_t)MROWS*DH1)      /* 25,600,000 */
#define EPS_ELEMS ((size_t)MROWS*DNOISE)
#define DNOISE 64

// ---------------- scratch (static device globals; no allocation) ------------
__device__ float g_h0[(size_t)MROWS*DH0];
__device__ float g_z0[(size_t)MROWS*DH0];
__device__ float g_h1[(size_t)MROWS*DH1];
__device__ float g_z1[(size_t)MROWS*DH1];
__device__ int   g_deg[NNODES];
__device__ int   g_rowptr[NNODES+1];
__device__ int   g_cursor[NNODES];
__device__ int   g_nbr[NEDGES];

// ---------------- f32x2 packed-math helpers (Blackwell FFMA2) ---------------
__device__ __forceinline__ unsigned long long pack2(float lo, float hi) {
    unsigned long long r;
    asm("mov.b64 %0, {%1, %2};" : "=l"(r) : "f"(lo), "f"(hi));
    return r;
}
__device__ __forceinline__ void unpack2(unsigned long long v, float& lo, float& hi) {
    asm("mov.b64 {%0, %1}, %2;" : "=f"(lo), "=f"(hi) : "l"(v));
}
__device__ __forceinline__ unsigned long long fma2(unsigned long long a,
                                                   unsigned long long b,
                                                   unsigned long long c) {
    unsigned long long d;
    asm("fma.rn.f32x2 %0, %1, %2, %3;" : "=l"(d) : "l"(a), "l"(b), "l"(c));
    return d;
}

// ---------------- kernel 1: build h0 = concat(X, eps) -----------------------
// one thread per float4; h0 row = 48 float4 (32 from X, 16 from eps)
__global__ void build_h0_kernel(const float4* __restrict__ X4,
                                const float4* __restrict__ E4,
                                float4* __restrict__ H4) {
    int idx = blockIdx.x * blockDim.x + threadIdx.x;
    const int total = MROWS * 48;
    if (idx >= total) return;
    int c  = idx % 48;
    int sn = idx / 48;              // s*N + n
    int n  = sn % NNODES;
    float4 v;
    if (c < 32) v = X4[(size_t)n * 32 + c];
    else        v = E4[(size_t)sn * 16 + (c - 32)];
    H4[idx] = v;
}

// ---------------- CSR build --------------------------------------------------
__global__ void zero_deg_kernel() {
    int i = blockIdx.x * blockDim.x + threadIdx.x;
    if (i < NNODES) g_deg[i] = 0;
}
__global__ void count_deg_kernel(const int* __restrict__ edst) {
    int e = blockIdx.x * blockDim.x + threadIdx.x;
    if (e < NEDGES) atomicAdd(&g_deg[edst[e]], 1);
}
__global__ void scan_kernel() {
    __shared__ int buf[1024];
    __shared__ int carry;
    int t = threadIdx.x;
    if (t == 0) carry = 0;
    __syncthreads();
    for (int base = 0; base < NNODES; base += 1024) {
        int v = (base + t < NNODES) ? g_deg[base + t] : 0;
        buf[t] = v;
        __syncthreads();
        #pragma unroll
        for (int off = 1; off < 1024; off <<= 1) {
            int x = (t >= off) ? buf[t - off] : 0;
            __syncthreads();
            buf[t] += x;
            __syncthreads();
        }
        int excl = buf[t] - v + carry;
        if (base + t < NNODES) { g_rowptr[base + t] = excl; g_cursor[base + t] = excl; }
        __syncthreads();
        if (t == 1023) carry += buf[1023];
        __syncthreads();
    }
    if (t == 0) g_rowptr[NNODES] = carry;
}
__global__ void fill_kernel(const int* __restrict__ esrc, const int* __restrict__ edst) {
    int e = blockIdx.x * blockDim.x + threadIdx.x;
    if (e < NEDGES) {
        int pos = atomicAdd(&g_cursor[edst[e]], 1);
        g_nbr[pos] = esrc[e];
    }
}

// ---------------- aggregation: z = (1+eps)*h + sum_{nbr} h -------------------
// one block per node, one thread per channel, both samples in registers
template <int D>
__global__ void agg_kernel(const float* __restrict__ h, float* __restrict__ z,
                           const float* __restrict__ eps_ptr) {
    int n = blockIdx.x;
    int c = threadIdx.x;                    // blockDim == D
    int beg = g_rowptr[n], end = g_rowptr[n + 1];
    float acc0 = 0.f, acc1 = 0.f;
    for (int i = beg; i < end; i++) {
        int s = g_nbr[i];
        acc0 += h[(size_t)s * D + c];
        acc1 += h[((size_t)NNODES + s) * D + c];
    }
    float e1p = 1.0f + *eps_ptr;
    z[(size_t)n * D + c]                     = fmaf(e1p, h[(size_t)n * D + c], acc0);
    z[((size_t)NNODES + n) * D + c]          = fmaf(e1p, h[((size_t)NNODES + n) * D + c], acc1);
}

// ---------------- GEMM: C[M,256] = relu(A[M,K] @ W[K,256] + b) ---------------
// BM=64, BN=128, BK=16, 256 threads, per-thread 4x8 via fma.rn.f32x2
template <int K>
__global__ void gemm_bias_relu(const float* __restrict__ A, const float* __restrict__ W,
                               const float* __restrict__ bias, float* __restrict__ C,
                               int M) {
    constexpr int NCOLS = 256;
    __shared__ __align__(16) float As[16][64];
    __shared__ __align__(16) float Bs[16][128];

    const int tid = threadIdx.x;
    const int tx = tid & 15;    // col group: 8 cols
    const int ty = tid >> 4;    // row group: 4 rows
    const int mBase = blockIdx.y * 64;
    const int nBase = blockIdx.x * 128;

    unsigned long long acc[4][4];
    #pragma unroll
    for (int i = 0; i < 4; i++)
        #pragma unroll
        for (int j = 0; j < 4; j++) acc[i][j] = 0ull;

    const int arow = tid >> 2;   // 0..63
    const int ac4  = tid & 3;    // 0..3

    for (int kt = 0; kt < K; kt += 16) {
        // A tile 64x16, transposed into As[k][m]
        float4 av = make_float4(0.f, 0.f, 0.f, 0.f);
        int gr = mBase + arow;
        if (gr < M) av = *(const float4*)&A[(size_t)gr * K + kt + ac4 * 4];
        As[ac4 * 4 + 0][arow] = av.x;
        As[ac4 * 4 + 1][arow] = av.y;
        As[ac4 * 4 + 2][arow] = av.z;
        As[ac4 * 4 + 3][arow] = av.w;
        // B tile 16x128
        #pragma unroll
        for (int r = 0; r < 2; r++) {
            int idx = tid + r * 256;
            int bk = idx >> 5, bc4 = idx & 31;
            *(float4*)&Bs[bk][bc4 * 4] =
                *(const float4*)&W[(size_t)(kt + bk) * NCOLS + nBase + bc4 * 4];
        }
        __syncthreads();
        #pragma unroll
        for (int kk = 0; kk < 16; kk++) {
            float4 a4 = *(const float4*)&As[kk][ty * 4];
            const unsigned long long* bp = (const unsigned long long*)&Bs[kk][tx * 8];
            unsigned long long b0 = bp[0], b1 = bp[1], b2 = bp[2], b3 = bp[3];
            unsigned long long aa;
            aa = pack2(a4.x, a4.x);
            acc[0][0] = fma2(aa, b0, acc[0][0]); acc[0][1] = fma2(aa, b1, acc[0][1]);
            acc[0][2] = fma2(aa, b2, acc[0][2]); acc[0][3] = fma2(aa, b3, acc[0][3]);
            aa = pack2(a4.y, a4.y);
            acc[1][0] = fma2(aa, b0, acc[1][0]); acc[1][1] = fma2(aa, b1, acc[1][1]);
            acc[1][2] = fma2(aa, b2, acc[1][2]); acc[1][3] = fma2(aa, b3, acc[1][3]);
            aa = pack2(a4.z, a4.z);
            acc[2][0] = fma2(aa, b0, acc[2][0]); acc[2][1] = fma2(aa, b1, acc[2][1]);
            acc[2][2] = fma2(aa, b2, acc[2][2]); acc[2][3] = fma2(aa, b3, acc[2][3]);
            aa = pack2(a4.w, a4.w);
            acc[3][0] = fma2(aa, b0, acc[3][0]); acc[3][1] = fma2(aa, b1, acc[3][1]);
            acc[3][2] = fma2(aa, b2, acc[3][2]); acc[3][3] = fma2(aa, b3, acc[3][3]);
        }
        __syncthreads();
    }

    // epilogue: bias + relu, vectorized stores
    float bv[8];
    #pragma unroll
    for (int j = 0; j < 8; j++) bv[j] = bias[nBase + tx * 8 + j];

    int grow = mBase + ty * 4;
    #pragma unroll
    for (int i = 0; i < 4; i++) {
        if (grow + i >= M) break;
        float o[8];
        #pragma unroll
        for (int j = 0; j < 4; j++) unpack2(acc[i][j], o[2 * j], o[2 * j + 1]);
        #pragma unroll
        for (int j = 0; j < 8; j++) o[j] = fmaxf(o[j] + bv[j], 0.f);
        float* cp = &C[(size_t)(grow + i) * NCOLS + nBase + tx * 8];
        *(float4*)cp       = make_float4(o[0], o[1], o[2], o[3]);
        *(float4*)(cp + 4) = make_float4(o[4], o[5], o[6], o[7]);
    }
}

// ---------------- launch -----------------------------------------------------
extern "C" void kernel_launch(void* const* d_in, const int* in_sizes, int n_in,
                              void* d_out, int out_size) {
    const float* X    = (const float*)d_in[0];
    const float* eps  = (const float*)d_in[1];
    const int*   esrc = (const int*)d_in[2];
    const int*   edst = (const int*)d_in[3];
    const float* W0   = (const float*)d_in[4];
    const float* b0   = (const float*)d_in[5];
    const float* W1   = (const float*)d_in[6];
    const float* b1   = (const float*)d_in[7];
    const float* e0   = (const float*)d_in[8];
    const float* e1   = (const float*)d_in[9];
    float* out = (float*)d_out;

    float *h0, *z0, *h1, *z1;
    cudaGetSymbolAddress((void**)&h0, g_h0);
    cudaGetSymbolAddress((void**)&z0, g_z0);
    cudaGetSymbolAddress((void**)&h1, g_h1);
    cudaGetSymbolAddress((void**)&z1, g_z1);

    // 1) h0 = concat(X broadcast, eps)
    {
        int total = MROWS * 48;
        build_h0_kernel<<<(total + 255) / 256, 256>>>(
            (const float4*)X, (const float4*)eps, (float4*)h0);
    }
    // 2) CSR build
    zero_deg_kernel<<<(NNODES + 255) / 256, 256>>>();
    count_deg_kernel<<<(NEDGES + 255) / 256, 256>>>(edst);
    scan_kernel<<<1, 1024>>>();
    fill_kernel<<<(NEDGES + 255) / 256, 256>>>(esrc, edst);

    // 3) layer 0
    agg_kernel<DH0><<<NNODES, DH0>>>(h0, z0, e0);
    gemm_bias_relu<DH0><<<dim3(2, (MROWS + 63) / 64), 256>>>(z0, W0, b0, h1, MROWS);

    // 4) layer 1 (outer relu is idempotent with the layer relu)
    agg_kernel<DH1><<<NNODES, DH1>>>(h1, z1, e1);
    gemm_bias_relu<DH1><<<dim3(2, (MROWS + 63) / 64), 256>>>(z1, W1, b1, out, MROWS);

    // 5) second output (epsilon) if the harness buffer includes it
    if ((size_t)out_size >= OUT_MAIN + EPS_ELEMS) {
        cudaMemcpyAsync(out + OUT_MAIN, eps, EPS_ELEMS * sizeof(float),
                        cudaMemcpyDeviceToDevice);
    }
}

// round 3
// speedup vs baseline: 1.4182x; 1.4182x over previous
#include <cuda_runtime.h>
#include <cstdint>

#define NNODES 50000
#define NEDGES 800000
#define SS 2
#define DIN 128
#define DNOISE 64
#define DH0 192   /* 128 + 64 */
#define DH1 256
#define MROWS (SS*NNODES)                 /* 100000 */
#define OUT_MAIN ((size_t)MROWS*DH1)      /* 25,600,000 */
#define EPS_ELEMS ((size_t)MROWS*DNOISE)
#define NSCANB ((NNODES + 255) / 256)     /* 196 */

// ---------------- scratch (static device globals; no allocation) ------------
__device__ float g_z0[(size_t)MROWS*DH0];
__device__ float g_h1[(size_t)MROWS*DH1];
__device__ float g_z1[(size_t)MROWS*DH1];
__device__ int   g_deg[NNODES];
__device__ int   g_rowptr[NNODES+1];
__device__ int   g_cursor[NNODES];
__device__ int   g_nbr[NEDGES];
__device__ int   g_bsum[256];

// ---------------- f32x2 packed-math helpers (Blackwell FFMA2) ---------------
__device__ __forceinline__ unsigned long long pack2(float lo, float hi) {
    unsigned long long r;
    asm("mov.b64 %0, {%1, %2};" : "=l"(r) : "f"(lo), "f"(hi));
    return r;
}
__device__ __forceinline__ void unpack2(unsigned long long v, float& lo, float& hi) {
    asm("mov.b64 {%0, %1}, %2;" : "=f"(lo), "=f"(hi) : "l"(v));
}
__device__ __forceinline__ unsigned long long fma2(unsigned long long a,
                                                   unsigned long long b,
                                                   unsigned long long c) {
    unsigned long long d;
    asm("fma.rn.f32x2 %0, %1, %2, %3;" : "=l"(d) : "l"(a), "l"(b), "l"(c));
    return d;
}

// ---------------- CSR build --------------------------------------------------
__global__ void zero_deg_kernel() {
    int i = blockIdx.x * blockDim.x + threadIdx.x;
    if (i < NNODES) g_deg[i] = 0;
}
__global__ void count_deg_kernel(const int* __restrict__ edst) {
    int e = blockIdx.x * blockDim.x + threadIdx.x;
    if (e < NEDGES) atomicAdd(&g_deg[edst[e]], 1);
}
// per-block inclusive scan of 256 degrees; writes local-exclusive + block sum
__global__ void block_scan_kernel() {
    __shared__ int sdata[256];
    int b = blockIdx.x, t = threadIdx.x;
    int idx = b * 256 + t;
    int v = (idx < NNODES) ? g_deg[idx] : 0;
    sdata[t] = v;
    __syncthreads();
    #pragma unroll
    for (int off = 1; off < 256; off <<= 1) {
        int x = (t >= off) ? sdata[t - off] : 0;
        __syncthreads();
        sdata[t] += x;
        __syncthreads();
    }
    if (idx < NNODES) g_rowptr[idx] = sdata[t] - v;   // local exclusive
    if (t == 255) g_bsum[b] = sdata[255];
}
// single-block exclusive scan of the 196 block sums
__global__ void scan_bsum_kernel() {
    __shared__ int sdata[256];
    int t = threadIdx.x;
    int v = (t < NSCANB) ? g_bsum[t] : 0;
    sdata[t] = v;
    __syncthreads();
    #pragma unroll
    for (int off = 1; off < 256; off <<= 1) {
        int x = (t >= off) ? sdata[t - off] : 0;
        __syncthreads();
        sdata[t] += x;
        __syncthreads();
    }
    g_bsum[t] = sdata[t] - v;   // exclusive
}
__global__ void add_off_kernel() {
    int idx = blockIdx.x * blockDim.x + threadIdx.x;
    if (idx < NNODES) {
        int r = g_rowptr[idx] + g_bsum[idx >> 8];
        g_rowptr[idx] = r;
        g_cursor[idx] = r;
    }
    if (idx == 0) g_rowptr[NNODES] = NEDGES;
}
__global__ void fill_kernel(const int* __restrict__ esrc, const int* __restrict__ edst) {
    int e = blockIdx.x * blockDim.x + threadIdx.x;
    if (e < NEDGES) {
        int pos = atomicAdd(&g_cursor[edst[e]], 1);
        g_nbr[pos] = esrc[e];
    }
}

// ---------------- fused layer-0 aggregation ----------------------------------
// z0[s,n,:] = (1+eps0)*concat(X[n],eps[s,n]) + sum_nbr concat(X[nbr],eps[s,nbr])
// threads 0..127 handle the X part (identical for both samples -> compute once),
// threads 128..191 handle the per-sample noise part.
__global__ void agg0_kernel(const float* __restrict__ X,
                            const float* __restrict__ eps,
                            float* __restrict__ z,
                            const float* __restrict__ eps0p) {
    int n = blockIdx.x;
    int c = threadIdx.x;                 // 0..191
    int beg = g_rowptr[n], end = g_rowptr[n + 1];
    float e1p = 1.0f + *eps0p;
    if (c < DIN) {
        float acc = 0.f;
        int i = beg;
        for (; i + 4 <= end; i += 4) {
            int s0 = g_nbr[i], s1 = g_nbr[i+1], s2 = g_nbr[i+2], s3 = g_nbr[i+3];
            float v0 = X[(size_t)s0 * DIN + c];
            float v1 = X[(size_t)s1 * DIN + c];
            float v2 = X[(size_t)s2 * DIN + c];
            float v3 = X[(size_t)s3 * DIN + c];
            acc += (v0 + v1) + (v2 + v3);
        }
        for (; i < end; i++) acc += X[(size_t)g_nbr[i] * DIN + c];
        float v = fmaf(e1p, X[(size_t)n * DIN + c], acc);
        z[(size_t)n * DH0 + c]                    = v;
        z[((size_t)NNODES + n) * DH0 + c]         = v;
    } else {
        int cc = c - DIN;
        const float* ep0 = eps;
        const float* ep1 = eps + (size_t)NNODES * DNOISE;
        float a0 = 0.f, a1 = 0.f;
        int i = beg;
        for (; i + 2 <= end; i += 2) {
            int s0 = g_nbr[i], s1 = g_nbr[i+1];
            float u0 = ep0[(size_t)s0 * DNOISE + cc];
            float u1 = ep0[(size_t)s1 * DNOISE + cc];
            float w0 = ep1[(size_t)s0 * DNOISE + cc];
            float w1 = ep1[(size_t)s1 * DNOISE + cc];
            a0 += u0 + u1;
            a1 += w0 + w1;
        }
        for (; i < end; i++) {
            int s = g_nbr[i];
            a0 += ep0[(size_t)s * DNOISE + cc];
            a1 += ep1[(size_t)s * DNOISE + cc];
        }
        z[(size_t)n * DH0 + c]            = fmaf(e1p, ep0[(size_t)n * DNOISE + cc], a0);
        z[((size_t)NNODES + n) * DH0 + c] = fmaf(e1p, ep1[(size_t)n * DNOISE + cc], a1);
    }
}

// ---------------- layer-1 aggregation: z = (1+eps)*h + sum_nbr h -------------
template <int D>
__global__ void agg_kernel(const float* __restrict__ h, float* __restrict__ z,
                           const float* __restrict__ eps_ptr) {
    int n = blockIdx.x;
    int c = threadIdx.x;                 // blockDim == D
    int beg = g_rowptr[n], end = g_rowptr[n + 1];
    const float* h1 = h + (size_t)NNODES * D;
    float a0 = 0.f, a1 = 0.f;
    int i = beg;
    for (; i + 2 <= end; i += 2) {
        int s0 = g_nbr[i], s1 = g_nbr[i+1];
        float u0 = h [(size_t)s0 * D + c];
        float u1 = h [(size_t)s1 * D + c];
        float w0 = h1[(size_t)s0 * D + c];
        float w1 = h1[(size_t)s1 * D + c];
        a0 += u0 + u1;
        a1 += w0 + w1;
    }
    for (; i < end; i++) {
        int s = g_nbr[i];
        a0 += h [(size_t)s * D + c];
        a1 += h1[(size_t)s * D + c];
    }
    float e1p = 1.0f + *eps_ptr;
    z[(size_t)n * D + c]                    = fmaf(e1p, h [(size_t)n * D + c], a0);
    z[((size_t)NNODES + n) * D + c]         = fmaf(e1p, h1[(size_t)n * D + c], a1);
}

// ---------------- GEMM: C[M,256] = relu(A[M,K] @ W[K,256] + b) ---------------
// BM=128, BN=128, BK=16, 256 threads, per-thread 8x8 via fma.rn.f32x2
template <int K>
__global__ void __launch_bounds__(256, 2)
gemm_bias_relu(const float* __restrict__ A, const float* __restrict__ W,
               const float* __restrict__ bias, float* __restrict__ C,
               int M) {
    constexpr int NCOLS = 256;
    __shared__ __align__(16) float As[16][128];
    __shared__ __align__(16) float Bs[16][128];

    const int tid = threadIdx.x;
    const int tx = tid & 15;    // col group: 8 cols
    const int ty = tid >> 4;    // row group: 8 rows
    const int mBase = blockIdx.y * 128;
    const int nBase = blockIdx.x * 128;

    unsigned long long acc[8][4];
    #pragma unroll
    for (int i = 0; i < 8; i++)
        #pragma unroll
        for (int j = 0; j < 4; j++) acc[i][j] = 0ull;

    const int arow  = tid >> 1;    // 0..127
    const int ahalf = tid & 1;     // k offset 0 / 8

    for (int kt = 0; kt < K; kt += 16) {
        // A tile 128x16 transposed into As[k][m]
        {
            int gr = mBase + arow;
            float4 v0 = make_float4(0.f, 0.f, 0.f, 0.f);
            float4 v1 = make_float4(0.f, 0.f, 0.f, 0.f);
            if (gr < M) {
                const float* ap = &A[(size_t)gr * K + kt + ahalf * 8];
                v0 = *(const float4*)ap;
                v1 = *(const float4*)(ap + 4);
            }
            int kb = ahalf * 8;
            As[kb + 0][arow] = v0.x; As[kb + 1][arow] = v0.y;
            As[kb + 2][arow] = v0.z; As[kb + 3][arow] = v0.w;
            As[kb + 4][arow] = v1.x; As[kb + 5][arow] = v1.y;
            As[kb + 6][arow] = v1.z; As[kb + 7][arow] = v1.w;
        }
        // B tile 16x128
        #pragma unroll
        for (int r = 0; r < 2; r++) {
            int idx = tid + r * 256;
            int bk = idx >> 5, bc4 = idx & 31;
            *(float4*)&Bs[bk][bc4 * 4] =
                *(const float4*)&W[(size_t)(kt + bk) * NCOLS + nBase + bc4 * 4];
        }
        __syncthreads();
        #pragma unroll
        for (int kk = 0; kk < 16; kk++) {
            float4 a0 = *(const float4*)&As[kk][ty * 8];
            float4 a1 = *(const float4*)&As[kk][ty * 8 + 4];
            const unsigned long long* bp = (const unsigned long long*)&Bs[kk][tx * 8];
            unsigned long long b0 = bp[0], b1 = bp[1], b2 = bp[2], b3 = bp[3];
            unsigned long long aa;
            aa = pack2(a0.x, a0.x);
            acc[0][0] = fma2(aa, b0, acc[0][0]); acc[0][1] = fma2(aa, b1, acc[0][1]);
            acc[0][2] = fma2(aa, b2, acc[0][2]); acc[0][3] = fma2(aa, b3, acc[0][3]);
            aa = pack2(a0.y, a0.y);
            acc[1][0] = fma2(aa, b0, acc[1][0]); acc[1][1] = fma2(aa, b1, acc[1][1]);
            acc[1][2] = fma2(aa, b2, acc[1][2]); acc[1][3] = fma2(aa, b3, acc[1][3]);
            aa = pack2(a0.z, a0.z);
            acc[2][0] = fma2(aa, b0, acc[2][0]); acc[2][1] = fma2(aa, b1, acc[2][1]);
            acc[2][2] = fma2(aa, b2, acc[2][2]); acc[2][3] = fma2(aa, b3, acc[2][3]);
            aa = pack2(a0.w, a0.w);
            acc[3][0] = fma2(aa, b0, acc[3][0]); acc[3][1] = fma2(aa, b1, acc[3][1]);
            acc[3][2] = fma2(aa, b2, acc[3][2]); acc[3][3] = fma2(aa, b3, acc[3][3]);
            aa = pack2(a1.x, a1.x);
            acc[4][0] = fma2(aa, b0, acc[4][0]); acc[4][1] = fma2(aa, b1, acc[4][1]);
            acc[4][2] = fma2(aa, b2, acc[4][2]); acc[4][3] = fma2(aa, b3, acc[4][3]);
            aa = pack2(a1.y, a1.y);
            acc[5][0] = fma2(aa, b0, acc[5][0]); acc[5][1] = fma2(aa, b1, acc[5][1]);
            acc[5][2] = fma2(aa, b2, acc[5][2]); acc[5][3] = fma2(aa, b3, acc[5][3]);
            aa = pack2(a1.z, a1.z);
            acc[6][0] = fma2(aa, b0, acc[6][0]); acc[6][1] = fma2(aa, b1, acc[6][1]);
            acc[6][2] = fma2(aa, b2, acc[6][2]); acc[6][3] = fma2(aa, b3, acc[6][3]);
            aa = pack2(a1.w, a1.w);
            acc[7][0] = fma2(aa, b0, acc[7][0]); acc[7][1] = fma2(aa, b1, acc[7][1]);
            acc[7][2] = fma2(aa, b2, acc[7][2]); acc[7][3] = fma2(aa, b3, acc[7][3]);
        }
        __syncthreads();
    }

    // epilogue: bias + relu, vectorized stores
    float bv[8];
    #pragma unroll
    for (int j = 0; j < 8; j++) bv[j] = bias[nBase + tx * 8 + j];

    int grow = mBase + ty * 8;
    #pragma unroll
    for (int i = 0; i < 8; i++) {
        if (grow + i >= M) break;
        float o[8];
        #pragma unroll
        for (int j = 0; j < 4; j++) unpack2(acc[i][j], o[2 * j], o[2 * j + 1]);
        #pragma unroll
        for (int j = 0; j < 8; j++) o[j] = fmaxf(o[j] + bv[j], 0.f);
        float* cp = &C[(size_t)(grow + i) * NCOLS + nBase + tx * 8];
        *(float4*)cp       = make_float4(o[0], o[1], o[2], o[3]);
        *(float4*)(cp + 4) = make_float4(o[4], o[5], o[6], o[7]);
    }
}

// ---------------- launch -----------------------------------------------------
extern "C" void kernel_launch(void* const* d_in, const int* in_sizes, int n_in,
                              void* d_out, int out_size) {
    const float* X    = (const float*)d_in[0];
    const float* eps  = (const float*)d_in[1];
    const int*   esrc = (const int*)d_in[2];
    const int*   edst = (const int*)d_in[3];
    const float* W0   = (const float*)d_in[4];
    const float* b0   = (const float*)d_in[5];
    const float* W1   = (const float*)d_in[6];
    const float* b1   = (const float*)d_in[7];
    const float* e0   = (const float*)d_in[8];
    const float* e1   = (const float*)d_in[9];
    float* out = (float*)d_out;

    float *z0, *h1, *z1;
    cudaGetSymbolAddress((void**)&z0, g_z0);
    cudaGetSymbolAddress((void**)&h1, g_h1);
    cudaGetSymbolAddress((void**)&z1, g_z1);

    // 1) CSR build (multi-block scan)
    zero_deg_kernel<<<(NNODES + 255) / 256, 256>>>();
    count_deg_kernel<<<(NEDGES + 255) / 256, 256>>>(edst);
    block_scan_kernel<<<NSCANB, 256>>>();
    scan_bsum_kernel<<<1, 256>>>();
    add_off_kernel<<<NSCANB, 256>>>();
    fill_kernel<<<(NEDGES + 255) / 256, 256>>>(esrc, edst);

    // 2) layer 0: fused concat + aggregation, then GEMM
    agg0_kernel<<<NNODES, DH0>>>(X, eps, z0, e0);
    gemm_bias_relu<DH0><<<dim3(2, (MROWS + 127) / 128), 256>>>(z0, W0, b0, h1, MROWS);

    // 3) layer 1 (outer relu is idempotent with the layer relu)
    agg_kernel<DH1><<<NNODES, DH1>>>(h1, z1, e1);
    gemm_bias_relu<DH1><<<dim3(2, (MROWS + 127) / 128), 256>>>(z1, W1, b1, out, MROWS);

    // 4) second output (epsilon) if the harness buffer includes it
    if ((size_t)out_size >= OUT_MAIN + EPS_ELEMS) {
        cudaMemcpyAsync(out + OUT_MAIN, eps, EPS_ELEMS * sizeof(float),
                        cudaMemcpyDeviceToDevice);
    }
}

// round 7
// speedup vs baseline: 2.1594x; 1.5226x over previous
#include <cuda_runtime.h>
#include <cuda_bf16.h>
#include <cstdint>

#define NNODES 50000
#define NEDGES 800000
#define SS 2
#define DIN 128
#define DNOISE 64
#define DH0 192   /* 128 + 64 */
#define DH1 256
#define MROWS (SS*NNODES)                 /* 100000 */
#define OUT_MAIN ((size_t)MROWS*DH1)      /* 25,600,000 */
#define EPS_ELEMS ((size_t)MROWS*DNOISE)
#define NSCANB ((NNODES + 255) / 256)     /* 196 */

// ---------------- scratch (static device globals; no allocation) ------------
__device__ float g_z0[(size_t)MROWS*DH0];
__device__ float g_h1[(size_t)MROWS*DH1];
__device__ float g_z1[(size_t)MROWS*DH1];
__device__ int   g_deg[NNODES];
__device__ int   g_rowptr[NNODES+1];
__device__ int   g_cursor[NNODES];
__device__ int   g_nbr[NEDGES];
__device__ int   g_bsum[256];
// pre-split weights, natural [K][256] layout, bf16 hi/lo
__device__ __nv_bfloat16 g_w0h[DH0*256];
__device__ __nv_bfloat16 g_w0l[DH0*256];
__device__ __nv_bfloat16 g_w1h[DH1*256];
__device__ __nv_bfloat16 g_w1l[DH1*256];

// ---------------- helpers ----------------------------------------------------
__device__ __forceinline__ uint32_t smem_u32(const void* p) {
    uint32_t a;
    asm("{ .reg .u64 t; cvta.to.shared.u64 t, %1; cvt.u32.u64 %0, t; }"
        : "=r"(a) : "l"(p));
    return a;
}
__device__ __forceinline__ void ldsm_x4(uint32_t* r, uint32_t a) {
    asm volatile("ldmatrix.sync.aligned.m8n8.x4.shared.b16 {%0,%1,%2,%3}, [%4];"
                 : "=r"(r[0]), "=r"(r[1]), "=r"(r[2]), "=r"(r[3]) : "r"(a));
}
__device__ __forceinline__ void ldsm_x4_t(uint32_t* r, uint32_t a) {
    asm volatile("ldmatrix.sync.aligned.m8n8.x4.trans.shared.b16 {%0,%1,%2,%3}, [%4];"
                 : "=r"(r[0]), "=r"(r[1]), "=r"(r[2]), "=r"(r[3]) : "r"(a));
}
__device__ __forceinline__ void mma_bf16(float* c, const uint32_t* a, const uint32_t* b) {
    asm volatile("mma.sync.aligned.m16n8k16.row.col.f32.bf16.bf16.f32 "
                 "{%0,%1,%2,%3}, {%4,%5,%6,%7}, {%8,%9}, {%0,%1,%2,%3};"
                 : "+f"(c[0]), "+f"(c[1]), "+f"(c[2]), "+f"(c[3])
                 : "r"(a[0]), "r"(a[1]), "r"(a[2]), "r"(a[3]),
                   "r"(b[0]), "r"(b[1]));
}

// ---------------- CSR build --------------------------------------------------
__global__ void zero_deg_kernel() {
    int i = blockIdx.x * blockDim.x + threadIdx.x;
    if (i < NNODES) g_deg[i] = 0;
}
__global__ void count_deg_kernel(const int* __restrict__ edst) {
    int e = blockIdx.x * blockDim.x + threadIdx.x;
    if (e < NEDGES) atomicAdd(&g_deg[edst[e]], 1);
}
__global__ void block_scan_kernel() {
    __shared__ int sdata[256];
    int b = blockIdx.x, t = threadIdx.x;
    int idx = b * 256 + t;
    int v = (idx < NNODES) ? g_deg[idx] : 0;
    sdata[t] = v;
    __syncthreads();
    #pragma unroll
    for (int off = 1; off < 256; off <<= 1) {
        int x = (t >= off) ? sdata[t - off] : 0;
        __syncthreads();
        sdata[t] += x;
        __syncthreads();
    }
    if (idx < NNODES) g_rowptr[idx] = sdata[t] - v;
    if (t == 255) g_bsum[b] = sdata[255];
}
__global__ void scan_bsum_kernel() {
    __shared__ int sdata[256];
    int t = threadIdx.x;
    int v = (t < NSCANB) ? g_bsum[t] : 0;
    sdata[t] = v;
    __syncthreads();
    #pragma unroll
    for (int off = 1; off < 256; off <<= 1) {
        int x = (t >= off) ? sdata[t - off] : 0;
        __syncthreads();
        sdata[t] += x;
        __syncthreads();
    }
    g_bsum[t] = sdata[t] - v;
}
__global__ void add_off_kernel() {
    int idx = blockIdx.x * blockDim.x + threadIdx.x;
    if (idx < NNODES) {
        int r = g_rowptr[idx] + g_bsum[idx >> 8];
        g_rowptr[idx] = r;
        g_cursor[idx] = r;
    }
    if (idx == 0) g_rowptr[NNODES] = NEDGES;
}
__global__ void fill_kernel(const int* __restrict__ esrc, const int* __restrict__ edst) {
    int e = blockIdx.x * blockDim.x + threadIdx.x;
    if (e < NEDGES) {
        int pos = atomicAdd(&g_cursor[edst[e]], 1);
        g_nbr[pos] = esrc[e];
    }
}

// ---------------- weight prep: bf16 hi/lo split, natural [K][256] layout -----
template <int K>
__global__ void prep_w_kernel(const float* __restrict__ W,
                              __nv_bfloat16* __restrict__ Wh,
                              __nv_bfloat16* __restrict__ Wl) {
    int idx = blockIdx.x * blockDim.x + threadIdx.x;
    if (idx >= K * 256) return;
    float v = W[idx];
    __nv_bfloat16 h = __float2bfloat16_rn(v);
    float r = v - __bfloat162float(h);
    Wh[idx] = h;
    Wl[idx] = __float2bfloat16_rn(r);
}

// ---------------- fused layer-0 aggregation ----------------------------------
__global__ void agg0_kernel(const float* __restrict__ X,
                            const float* __restrict__ eps,
                            float* __restrict__ z,
                            const float* __restrict__ eps0p) {
    int n = blockIdx.x;
    int c = threadIdx.x;                 // 0..191
    int beg = g_rowptr[n], end = g_rowptr[n + 1];
    float e1p = 1.0f + *eps0p;
    if (c < DIN) {
        float acc = 0.f;
        int i = beg;
        for (; i + 4 <= end; i += 4) {
            int s0 = g_nbr[i], s1 = g_nbr[i+1], s2 = g_nbr[i+2], s3 = g_nbr[i+3];
            float v0 = X[(size_t)s0 * DIN + c];
            float v1 = X[(size_t)s1 * DIN + c];
            float v2 = X[(size_t)s2 * DIN + c];
            float v3 = X[(size_t)s3 * DIN + c];
            acc += (v0 + v1) + (v2 + v3);
        }
        for (; i < end; i++) acc += X[(size_t)g_nbr[i] * DIN + c];
        float v = fmaf(e1p, X[(size_t)n * DIN + c], acc);
        z[(size_t)n * DH0 + c]            = v;
        z[((size_t)NNODES + n) * DH0 + c] = v;
    } else {
        int cc = c - DIN;
        const float* ep0 = eps;
        const float* ep1 = eps + (size_t)NNODES * DNOISE;
        float a0 = 0.f, a1 = 0.f;
        int i = beg;
        for (; i + 2 <= end; i += 2) {
            int s0 = g_nbr[i], s1 = g_nbr[i+1];
            float u0 = ep0[(size_t)s0 * DNOISE + cc];
            float u1 = ep0[(size_t)s1 * DNOISE + cc];
            float w0 = ep1[(size_t)s0 * DNOISE + cc];
            float w1 = ep1[(size_t)s1 * DNOISE + cc];
            a0 += u0 + u1;
            a1 += w0 + w1;
        }
        for (; i < end; i++) {
            int s = g_nbr[i];
            a0 += ep0[(size_t)s * DNOISE + cc];
            a1 += ep1[(size_t)s * DNOISE + cc];
        }
        z[(size_t)n * DH0 + c]            = fmaf(e1p, ep0[(size_t)n * DNOISE + cc], a0);
        z[((size_t)NNODES + n) * DH0 + c] = fmaf(e1p, ep1[(size_t)n * DNOISE + cc], a1);
    }
}

// ---------------- layer-1 aggregation ----------------------------------------
template <int D>
__global__ void agg_kernel(const float* __restrict__ h, float* __restrict__ z,
                           const float* __restrict__ eps_ptr) {
    int n = blockIdx.x;
    int c = threadIdx.x;
    int beg = g_rowptr[n], end = g_rowptr[n + 1];
    const float* h1 = h + (size_t)NNODES * D;
    float a0 = 0.f, a1 = 0.f;
    int i = beg;
    for (; i + 2 <= end; i += 2) {
        int s0 = g_nbr[i], s1 = g_nbr[i+1];
        float u0 = h [(size_t)s0 * D + c];
        float u1 = h [(size_t)s1 * D + c];
        float w0 = h1[(size_t)s0 * D + c];
        float w1 = h1[(size_t)s1 * D + c];
        a0 += u0 + u1;
        a1 += w0 + w1;
    }
    for (; i < end; i++) {
        int s = g_nbr[i];
        a0 += h [(size_t)s * D + c];
        a1 += h1[(size_t)s * D + c];
    }
    float e1p = 1.0f + *eps_ptr;
    z[(size_t)n * D + c]            = fmaf(e1p, h [(size_t)n * D + c], a0);
    z[((size_t)NNODES + n) * D + c] = fmaf(e1p, h1[(size_t)n * D + c], a1);
}

// ---------------- bf16x3 mma.sync GEMM: C = relu(A[M,K] @ W[K,256] + b) ------
// BM=128, BN=128, BK=32. 8 warps: 4 (M) x 2 (N); warp tile 32x64.
// A split hi/lo in-register during tile load; W pre-split.
// smem (halves): Ah 128x40 pad, Al 128x40, Bh 32x136 pad, Bl 32x136; x2 stages.
template <int K>
__global__ void __launch_bounds__(256, 1)
gemm_mma(const float* __restrict__ A, const __nv_bfloat16* __restrict__ Wh,
         const __nv_bfloat16* __restrict__ Wl, const float* __restrict__ bias,
         float* __restrict__ C, int M) {
    constexpr int NST = K / 32;
    constexpr int AH = 0, AL = 5120, BH = 10240, BL = 14592, STG = 18944; // halves

    extern __shared__ __align__(16) __nv_bfloat16 sh[];
    const uint32_t shb = smem_u32(sh);

    const int tid = threadIdx.x;
    const int lane = tid & 31, wid = tid >> 5;
    const int wm = wid & 3;          // 0..3 -> 32-row slice
    const int wn = wid >> 2;         // 0..1 -> 64-col slice
    const int mBase = blockIdx.x * 128;
    const int nCta = blockIdx.y * 128;

    float acc[2][8][4];
    #pragma unroll
    for (int i = 0; i < 2; i++)
        #pragma unroll
        for (int j = 0; j < 8; j++)
            #pragma unroll
            for (int q = 0; q < 4; q++) acc[i][j][q] = 0.f;

    float4 pa[4];
    uint4 pbh[2], pbl[2];

    auto load_g = [&](int s) {
        const int kt = s * 32;
        #pragma unroll
        for (int i = 0; i < 4; i++) {
            int idx = i * 256 + tid;
            int row = idx >> 3, c4 = idx & 7;
            int gr = mBase + row;
            pa[i] = (gr < M) ? *(const float4*)&A[(size_t)gr * K + kt + c4 * 4]
                             : make_float4(0.f, 0.f, 0.f, 0.f);
        }
        #pragma unroll
        for (int i = 0; i < 2; i++) {
            int idx = i * 256 + tid;
            int brow = idx >> 4, c8 = idx & 15;
            size_t g = (size_t)(kt + brow) * 256 + nCta + c8 * 8;
            pbh[i] = *(const uint4*)&Wh[g];
            pbl[i] = *(const uint4*)&Wl[g];
        }
    };

    auto store_s = [&](int buf) {
        __nv_bfloat16* base = sh + buf * STG;
        #pragma unroll
        for (int i = 0; i < 4; i++) {
            int idx = i * 256 + tid;
            int row = idx >> 3, c4 = idx & 7;
            const float* v = (const float*)&pa[i];
            uint32_t hh[2], ll[2];
            #pragma unroll
            for (int p = 0; p < 2; p++) {
                float x0 = v[2 * p], x1 = v[2 * p + 1];
                __nv_bfloat16 h0 = __float2bfloat16_rn(x0);
                __nv_bfloat16 h1 = __float2bfloat16_rn(x1);
                float l0 = x0 - __bfloat162float(h0);
                float l1 = x1 - __bfloat162float(h1);
                __nv_bfloat162 hp = __floats2bfloat162_rn(x0, x1); // .x=lo addr
                (void)hp;
                __nv_bfloat162 hw; hw.x = h0; hw.y = h1;
                __nv_bfloat162 lw; lw.x = __float2bfloat16_rn(l0);
                lw.y = __float2bfloat16_rn(l1);
                hh[p] = *(uint32_t*)&hw;
                ll[p] = *(uint32_t*)&lw;
            }
            *(uint2*)&base[AH + row * 40 + c4 * 4] = make_uint2(hh[0], hh[1]);
            *(uint2*)&base[AL + row * 40 + c4 * 4] = make_uint2(ll[0], ll[1]);
        }
        #pragma unroll
        for (int i = 0; i < 2; i++) {
            int idx = i * 256 + tid;
            int brow = idx >> 4, c8 = idx & 15;
            *(uint4*)&base[BH + brow * 136 + c8 * 8] = pbh[i];
            *(uint4*)&base[BL + brow * 136 + c8 * 8] = pbl[i];
        }
    };

    auto compute = [&](int buf) {
        const uint32_t base = shb + (uint32_t)buf * STG * 2;   // bytes
        #pragma unroll
        for (int k16 = 0; k16 < 2; k16++) {
            const int krow = k16 * 16;
            uint32_t ah[2][4], al[2][4], bh[8][2], bl[8][2];
            #pragma unroll
            for (int i = 0; i < 2; i++) {
                uint32_t ra = base + (uint32_t)(AH * 2) +
                    (uint32_t)(((wm * 32 + i * 16 + (lane & 15)) * 40 +
                                krow + ((lane >> 4) << 3)) * 2);
                ldsm_x4(ah[i], ra);
                ldsm_x4(al[i], ra + (uint32_t)((AL - AH) * 2));
            }
            #pragma unroll
            for (int j = 0; j < 4; j++) {
                uint32_t rb = base + (uint32_t)(BH * 2) +
                    (uint32_t)(((krow + (lane & 15)) * 136 +
                                wn * 64 + j * 16 + ((lane >> 4) << 3)) * 2);
                uint32_t t[4];
                ldsm_x4_t(t, rb);
                bh[2*j][0] = t[0]; bh[2*j][1] = t[1];
                bh[2*j+1][0] = t[2]; bh[2*j+1][1] = t[3];
                ldsm_x4_t(t, rb + (uint32_t)((BL - BH) * 2));
                bl[2*j][0] = t[0]; bl[2*j][1] = t[1];
                bl[2*j+1][0] = t[2]; bl[2*j+1][1] = t[3];
            }
            #pragma unroll
            for (int i = 0; i < 2; i++)
                #pragma unroll
                for (int j = 0; j < 8; j++) {
                    mma_bf16(acc[i][j], ah[i], bh[j]);
                    mma_bf16(acc[i][j], al[i], bh[j]);
                    mma_bf16(acc[i][j], ah[i], bl[j]);
                }
        }
    };

    load_g(0);
    store_s(0);
    __syncthreads();
    #pragma unroll
    for (int s = 0; s < NST; s++) {
        if (s + 1 < NST) load_g(s + 1);
        compute(s & 1);
        if (s + 1 < NST) {
            store_s((s + 1) & 1);
            __syncthreads();
        }
    }

    // epilogue: bias + relu, float2 stores per c-fragment pair
    const int trow = lane >> 2;
    const int tcol = (lane & 3) * 2;
    #pragma unroll
    for (int i = 0; i < 2; i++) {
        int r0 = mBase + wm * 32 + i * 16 + trow;
        #pragma unroll
        for (int j = 0; j < 8; j++) {
            int col = nCta + wn * 64 + j * 8 + tcol;
            float2 bv = *(const float2*)&bias[col];
            if (r0 < M) {
                float2 o;
                o.x = fmaxf(acc[i][j][0] + bv.x, 0.f);
                o.y = fmaxf(acc[i][j][1] + bv.y, 0.f);
                *(float2*)&C[(size_t)r0 * 256 + col] = o;
            }
            if (r0 + 8 < M) {
                float2 o;
                o.x = fmaxf(acc[i][j][2] + bv.x, 0.f);
                o.y = fmaxf(acc[i][j][3] + bv.y, 0.f);
                *(float2*)&C[(size_t)(r0 + 8) * 256 + col] = o;
            }
        }
    }
}

// ---------------- launch -----------------------------------------------------
extern "C" void kernel_launch(void* const* d_in, const int* in_sizes, int n_in,
                              void* d_out, int out_size) {
    const float* X    = (const float*)d_in[0];
    const float* eps  = (const float*)d_in[1];
    const int*   esrc = (const int*)d_in[2];
    const int*   edst = (const int*)d_in[3];
    const float* W0   = (const float*)d_in[4];
    const float* b0   = (const float*)d_in[5];
    const float* W1   = (const float*)d_in[6];
    const float* b1   = (const float*)d_in[7];
    const float* e0   = (const float*)d_in[8];
    const float* e1   = (const float*)d_in[9];
    float* out = (float*)d_out;

    float *z0, *h1, *z1;
    __nv_bfloat16 *w0h, *w0l, *w1h, *w1l;
    cudaGetSymbolAddress((void**)&z0, g_z0);
    cudaGetSymbolAddress((void**)&h1, g_h1);
    cudaGetSymbolAddress((void**)&z1, g_z1);
    cudaGetSymbolAddress((void**)&w0h, g_w0h);
    cudaGetSymbolAddress((void**)&w0l, g_w0l);
    cudaGetSymbolAddress((void**)&w1h, g_w1h);
    cudaGetSymbolAddress((void**)&w1l, g_w1l);

    const int DYN = 2 * 18944 * 2;   // 75776 bytes
    cudaFuncSetAttribute(gemm_mma<DH0>, cudaFuncAttributeMaxDynamicSharedMemorySize, DYN);
    cudaFuncSetAttribute(gemm_mma<DH1>, cudaFuncAttributeMaxDynamicSharedMemorySize, DYN);

    // 1) CSR build + weight prep
    zero_deg_kernel<<<(NNODES + 255) / 256, 256>>>();
    count_deg_kernel<<<(NEDGES + 255) / 256, 256>>>(edst);
    block_scan_kernel<<<NSCANB, 256>>>();
    scan_bsum_kernel<<<1, 256>>>();
    add_off_kernel<<<NSCANB, 256>>>();
    fill_kernel<<<(NEDGES + 255) / 256, 256>>>(esrc, edst);
    prep_w_kernel<DH0><<<(DH0 * 256 + 255) / 256, 256>>>(W0, w0h, w0l);
    prep_w_kernel<DH1><<<(DH1 * 256 + 255) / 256, 256>>>(W1, w1h, w1l);

    dim3 ggrid((MROWS + 127) / 128, 2);

    // 2) layer 0
    agg0_kernel<<<NNODES, DH0>>>(X, eps, z0, e0);
    gemm_mma<DH0><<<ggrid, 256, DYN>>>(z0, w0h, w0l, b0, h1, MROWS);

    // 3) layer 1 (outer relu idempotent with layer relu)
    agg_kernel<DH1><<<NNODES, DH1>>>(h1, z1, e1);
    gemm_mma<DH1><<<ggrid, 256, DYN>>>(z1, w1h, w1l, b1, out, MROWS);

    // 4) second output (epsilon) if the harness buffer includes it
    if ((size_t)out_size >= OUT_MAIN + EPS_ELEMS) {
        cudaMemcpyAsync(out + OUT_MAIN, eps, EPS_ELEMS * sizeof(float),
                        cudaMemcpyDeviceToDevice);
    }
}